// round 10
// baseline (speedup 1.0000x reference)
#include <cuda_runtime.h>
#include <cuda_bf16.h>
#include <cstdint>

#define NROWS   32768
#define KCODES  2048
#define CDIM    256
#define ZQN     8388608
#define LOSS_OFF 8388608
#define IDX_OFF  8388609
#define NPART   2048
#define CAND_MAX 32
#define FILT_EPS 2.5e-3f

// B tile row stride in bf16 (256 data + 8 pad; 528B = 33*16, !=0 mod 128 -> conflict-free frags)
#define RS 264

// ---- scratch (device globals; no allocation allowed) ----------------------
__device__ float          g_se[KCODES];
__device__ float          g_sz[NROWS];
__device__ int            g_idx[NROWS];
__device__ double         g_part[NPART];
__device__ __nv_bfloat16  g_embh[KCODES * RS];   // emb in bf16, padded rows
__device__ int            g_cnt[NROWS];
__device__ int            g_cand[NROWS * CAND_MAX];

// ---- helpers ---------------------------------------------------------------
__device__ __forceinline__ uint32_t smem_u32(const void* p) {
    uint32_t a;
    asm("{ .reg .u64 t; cvta.to.shared.u64 t, %1; cvt.u32.u64 %0, t; }"
        : "=r"(a) : "l"(p));
    return a;
}
__device__ __forceinline__ void cp16(uint32_t dst, const void* src) {
    asm volatile("cp.async.cg.shared.global [%0], [%1], 16;"
                 :: "r"(dst), "l"(src) : "memory");
}
#define CP_COMMIT() asm volatile("cp.async.commit_group;" ::: "memory")
#define CP_WAIT1()  asm volatile("cp.async.wait_group 1;" ::: "memory")
#define CP_WAIT0()  asm volatile("cp.async.wait_group 0;" ::: "memory")

// bf16 warp MMA m16n8k16 (plain Ampere-era PTX; valid on sm_103 target)
__device__ __forceinline__ void mma16816(float* d, const uint32_t* a, const uint32_t* b) {
    asm volatile(
        "mma.sync.aligned.m16n8k16.row.col.f32.bf16.bf16.f32 "
        "{%0,%1,%2,%3}, {%4,%5,%6,%7}, {%8,%9}, {%0,%1,%2,%3};"
        : "+f"(d[0]), "+f"(d[1]), "+f"(d[2]), "+f"(d[3])
        : "r"(a[0]), "r"(a[1]), "r"(a[2]), "r"(a[3]), "r"(b[0]), "r"(b[1]));
}

// ---- smem layout for k_filter (bytes) --------------------------------------
#define SA    0                 // A: 128 x RS bf16                    67584
#define SB    67584             // B: 2 x (128 x RS) bf16             135168
#define SSE   202752            // se staging [2][128] f32              1024
#define SRM   203776            // rowmin [128][4] f32                  2048
#define SCAND 205824            // candidates [128][32] int            16384
#define SCNT  222208            // counts [128] int                      512
#define SMEM_F 222720
#define BUFE  (128 * RS)        // bf16 elems per B buffer

// ===========================================================================
// per-code / per-row squared norms (exact fp32, same sequences as R1)
// ===========================================================================
__global__ void k_se(const float* __restrict__ emb) {
    int k = blockIdx.x * 128 + threadIdx.x;
    const float4* e = (const float4*)(emb + (size_t)k * CDIM);
    float s = 0.f;
#pragma unroll 8
    for (int i = 0; i < CDIM / 4; i++) {
        float4 v = e[i];
        s += v.x * v.x; s += v.y * v.y; s += v.z * v.z; s += v.w * v.w;
    }
    g_se[k] = s;
}

__global__ void k_sz(const float* __restrict__ z) {
    int n = blockIdx.x * 256 + threadIdx.x;
    int b = n >> 12, s = n & 4095;
    const float* p = z + (size_t)b * 1048576 + s;
    float acc = 0.f;
#pragma unroll 8
    for (int c = 0; c < CDIM; c++) {
        float v = p[(size_t)c * 4096];
        acc += v * v;
    }
    g_sz[n] = acc;
}

// emb fp32 -> bf16 into padded [code][RS] layout
__global__ void k_cvt(const float* __restrict__ emb) {
    int g = blockIdx.x * 256 + threadIdx.x;       // 32768 groups of 16 elems
    int code = g >> 4, m = g & 15;
    const float4* src = (const float4*)(emb + (size_t)code * CDIM + m * 16);
    __nv_bfloat162 v[8];
#pragma unroll
    for (int i = 0; i < 4; i++) {
        float4 f = src[i];
        v[2 * i]     = __floats2bfloat162_rn(f.x, f.y);
        v[2 * i + 1] = __floats2bfloat162_rn(f.z, f.w);
    }
    __nv_bfloat162* dst = (__nv_bfloat162*)(g_embh + (size_t)code * RS + m * 16);
#pragma unroll
    for (int i = 0; i < 8; i++) dst[i] = v[i];
}

// ===========================================================================
// Warp-MMA bf16 distance filter. 256 CTAs x 128 rows x 2048 codes.
// 16 code tiles of 128; warp grid 2(M) x 4(N); warp tile 64x32; k-steps 16.
// Per tile: update per-row running min (quad shfl + exclusive smem slots),
// sync, emit candidates with tt < min4 + eps.
// ===========================================================================
__global__ __launch_bounds__(256, 1) void k_filter(const float* __restrict__ z) {
    extern __shared__ char smem[];
    __nv_bfloat16* As   = (__nv_bfloat16*)(smem + SA);
    __nv_bfloat16* Bs   = (__nv_bfloat16*)(smem + SB);
    float*         se_s = (float*)(smem + SSE);
    float*         rowm = (float*)(smem + SRM);
    int*           scand = (int*)(smem + SCAND);
    int*           scnt  = (int*)(smem + SCNT);
    const uint32_t sbase = smem_u32(smem);

    const int tid = threadIdx.x, lane = tid & 31, wid = tid >> 5;
    const int qr = lane >> 2, qc = lane & 3;
    const int WM = wid & 1, WN = wid >> 1;          // 2 x 4 warp grid
    const int n0 = blockIdx.x * 128;

    // ---- A fill: z rows n0..n0+127 -> bf16 As[row][c] (coalesced over row)
    {
        const float* zb = z + ((size_t)(n0 >> 12)) * 1048576 + (n0 & 4095);
#pragma unroll 8
        for (int i = 0; i < 128; i++) {
            int u = tid + i * 256;                  // 0..32767
            int row = u & 127, c = u >> 7;
            As[row * RS + c] = __float2bfloat16(zb[(size_t)c * 4096 + row]);
        }
    }
    // init rowmin / counts
    if (tid < 128) scnt[tid] = 0;
    for (int i = tid; i < 512; i += 256) rowm[i] = 1e30f;

    // ---- B tile async loader (16B chunk = 8 bf16 elements) ----
    auto issueB = [&](int t) {
        const __nv_bfloat16* src = g_embh + (size_t)t * 128 * RS;
        uint32_t dbase = sbase + SB + (t & 1) * (BUFE * 2);
#pragma unroll
        for (int i = 0; i < 16; i++) {
            int u = tid + i * 256;                  // 0..4095 16B-chunks
            int n = u >> 5, m = u & 31;             // row, chunk-in-row (32x16B=512B)
            cp16(dbase + (uint32_t)(n * RS * 2 + m * 16),
                 (const void*)(src + (size_t)n * RS + m * 8));
        }
        if (tid < 128) se_s[(t & 1) * 128 + tid] = g_se[t * 128 + tid];
    };

    issueB(0);
    CP_COMMIT();

    for (int t = 0; t < 16; t++) {
        if (t < 15) { issueB(t + 1); CP_COMMIT(); CP_WAIT1(); }
        else        { CP_WAIT0(); }
        __syncthreads();                            // tile t data + A visible

        const __nv_bfloat16* Bp = Bs + (t & 1) * BUFE;
        float acc[4][4][4];
#pragma unroll
        for (int mf = 0; mf < 4; mf++)
#pragma unroll
            for (int nf = 0; nf < 4; nf++)
#pragma unroll
                for (int i = 0; i < 4; i++) acc[mf][nf][i] = 0.f;

#pragma unroll
        for (int ks = 0; ks < 16; ks++) {
            const int k0 = ks * 16;
            uint32_t a[4][4], b[4][2];
#pragma unroll
            for (int mf = 0; mf < 4; mf++) {
                const __nv_bfloat16* ap =
                    As + (64 * WM + 16 * mf + qr) * RS + k0 + 2 * qc;
                a[mf][0] = *(const uint32_t*)(ap);
                a[mf][1] = *(const uint32_t*)(ap + 8 * RS);
                a[mf][2] = *(const uint32_t*)(ap + 8);
                a[mf][3] = *(const uint32_t*)(ap + 8 * RS + 8);
            }
#pragma unroll
            for (int nf = 0; nf < 4; nf++) {
                const __nv_bfloat16* bp =
                    Bp + (32 * WN + 8 * nf + qr) * RS + k0 + 2 * qc;
                b[nf][0] = *(const uint32_t*)(bp);
                b[nf][1] = *(const uint32_t*)(bp + 8);
            }
#pragma unroll
            for (int mf = 0; mf < 4; mf++)
#pragma unroll
                for (int nf = 0; nf < 4; nf++)
                    mma16816(acc[mf][nf], a[mf], b[nf]);
        }

        // ---- per-row min fold (tt = se - 2*acc; sz omitted: row-constant)
        const float* sep = se_s + (t & 1) * 128;
        float rmin[4][2];
#pragma unroll
        for (int mf = 0; mf < 4; mf++) { rmin[mf][0] = 1e30f; rmin[mf][1] = 1e30f; }
#pragma unroll
        for (int mf = 0; mf < 4; mf++)
#pragma unroll
            for (int nf = 0; nf < 4; nf++) {
                int cb = 32 * WN + 8 * nf + 2 * qc;
                float s0 = sep[cb], s1 = sep[cb + 1];
                float t00 = fmaf(-2.f, acc[mf][nf][0], s0);
                float t01 = fmaf(-2.f, acc[mf][nf][1], s1);
                float t10 = fmaf(-2.f, acc[mf][nf][2], s0);
                float t11 = fmaf(-2.f, acc[mf][nf][3], s1);
                rmin[mf][0] = fminf(rmin[mf][0], fminf(t00, t01));
                rmin[mf][1] = fminf(rmin[mf][1], fminf(t10, t11));
            }
#pragma unroll
        for (int mf = 0; mf < 4; mf++)
#pragma unroll
            for (int h = 0; h < 2; h++) {
                float v = rmin[mf][h];
                v = fminf(v, __shfl_xor_sync(0xffffffffu, v, 1));
                v = fminf(v, __shfl_xor_sync(0xffffffffu, v, 2));
                if (qc == 0) {                      // exclusive (row, WN) owner
                    int r = 64 * WM + 16 * mf + qr + 8 * h;
                    float* p = &rowm[r * 4 + WN];
                    *p = fminf(*p, v);
                }
            }
        __syncthreads();                            // all min slots updated

        // ---- emission pass (conservative superset vs running min)
#pragma unroll
        for (int mf = 0; mf < 4; mf++)
#pragma unroll
            for (int h = 0; h < 2; h++) {
                int r = 64 * WM + 16 * mf + qr + 8 * h;
                const float* rp = rowm + r * 4;
                float m4 = fminf(fminf(rp[0], rp[1]), fminf(rp[2], rp[3])) + FILT_EPS;
#pragma unroll
                for (int nf = 0; nf < 4; nf++) {
                    int cb = 32 * WN + 8 * nf + 2 * qc;
                    float t0 = fmaf(-2.f, acc[mf][nf][2 * h],     sep[cb]);
                    float t1 = fmaf(-2.f, acc[mf][nf][2 * h + 1], sep[cb + 1]);
                    if (t0 < m4) {
                        int p = atomicAdd(&scnt[r], 1);
                        if (p < CAND_MAX) scand[r * CAND_MAX + p] = t * 128 + cb;
                    }
                    if (t1 < m4) {
                        int p = atomicAdd(&scnt[r], 1);
                        if (p < CAND_MAX) scand[r * CAND_MAX + p] = t * 128 + cb + 1;
                    }
                }
            }
        __syncthreads();                            // emits done; safe to overwrite
    }

    if (tid < 128) g_cnt[n0 + tid] = scnt[tid];
    for (int i = tid; i < 128 * CAND_MAX; i += 256)
        g_cand[(size_t)n0 * CAND_MAX + i] = scand[i];
}

// ===========================================================================
// Exact fp32 rescore over candidates — bit-identical math to the R1 kernel:
// serial c=0..255 FMA, d = (s_z + s_e) - 2*acc, lexicographic (d, idx) min.
// ===========================================================================
__global__ __launch_bounds__(256) void k_rescore(const float* __restrict__ z,
                                                 const float* __restrict__ emb) {
    __shared__ float zrow[8][256];
    const int tid = threadIdx.x, w = tid >> 5, lane = tid & 31;
    const int n0 = blockIdx.x * 8;
    const int bb = n0 >> 12;
    const float* zb = z + (size_t)bb * 1048576 + (n0 & 4095);
    {
        int r = tid & 7, cp = tid >> 3;
#pragma unroll
        for (int jj = 0; jj < 8; jj++) {
            int c = cp + jj * 32;
            zrow[r][c] = zb[(size_t)c * 4096 + r];
        }
    }
    __syncthreads();

    const int n = n0 + w;
    const int cnt = g_cnt[n];
    const float sz = g_sz[n];
    float bd = 1e38f;
    int bi = 0x7fffffff;

    if (cnt <= CAND_MAX) {
        for (int q = lane; q < cnt; q += 32) {
            int k = g_cand[(size_t)n * CAND_MAX + q];
            const float* e = emb + (size_t)k * 256;
            float acc = 0.f;
            for (int c = 0; c < 256; c++) acc = fmaf(zrow[w][c], e[c], acc);
            float d = (sz + g_se[k]) - 2.0f * acc;
            if (d < bd || (d == bd && k < bi)) { bd = d; bi = k; }
        }
    } else {
        for (int k = lane; k < KCODES; k += 32) {
            const float* e = emb + (size_t)k * 256;
            float acc = 0.f;
            for (int c = 0; c < 256; c++) acc = fmaf(zrow[w][c], e[c], acc);
            float d = (sz + g_se[k]) - 2.0f * acc;
            if (d < bd || (d == bd && k < bi)) { bd = d; bi = k; }
        }
    }
#pragma unroll
    for (int off = 16; off > 0; off >>= 1) {
        float d2 = __shfl_down_sync(0xffffffffu, bd, off);
        int i2 = __shfl_down_sync(0xffffffffu, bi, off);
        if (d2 < bd || (d2 == bd && i2 < bi)) { bd = d2; bi = i2; }
    }
    if (lane == 0) g_idx[n] = bi;
}

// ===========================================================================
// gather + z_q_st + loss partials (2 rows per warp)
// ===========================================================================
__global__ __launch_bounds__(256) void k_gather(const float* __restrict__ z,
                                                const float* __restrict__ emb,
                                                float* __restrict__ out) {
    const int tid = threadIdx.x, lane = tid & 31, w = tid >> 5;
    const int n = blockIdx.x * 16 + w * 2;
    const int iA = g_idx[n], iB = g_idx[n + 1];
    const size_t eoA = (size_t)iA * 256 + lane * 8;
    const size_t eoB = (size_t)iB * 256 + lane * 8;
    const size_t zoA = (size_t)n * 256 + lane * 8;
    const size_t zoB = zoA + 256;

    float4 a0 = *(const float4*)(emb + eoA), a1 = *(const float4*)(emb + eoA + 4);
    float4 b0 = *(const float4*)(emb + eoB), b1 = *(const float4*)(emb + eoB + 4);
    float4 x0 = *(const float4*)(z + zoA),   x1 = *(const float4*)(z + zoA + 4);
    float4 y0 = *(const float4*)(z + zoB),   y1 = *(const float4*)(z + zoB + 4);

    float dA[8] = {a0.x - x0.x, a0.y - x0.y, a0.z - x0.z, a0.w - x0.w,
                   a1.x - x1.x, a1.y - x1.y, a1.z - x1.z, a1.w - x1.w};
    float dB[8] = {b0.x - y0.x, b0.y - y0.y, b0.z - y0.z, b0.w - y0.w,
                   b1.x - y1.x, b1.y - y1.y, b1.z - y1.z, b1.w - y1.w};

    float4 o;
    o.x = x0.x + dA[0]; o.y = x0.y + dA[1]; o.z = x0.z + dA[2]; o.w = x0.w + dA[3];
    *(float4*)(out + zoA) = o;
    o.x = x1.x + dA[4]; o.y = x1.y + dA[5]; o.z = x1.z + dA[6]; o.w = x1.w + dA[7];
    *(float4*)(out + zoA + 4) = o;
    o.x = y0.x + dB[0]; o.y = y0.y + dB[1]; o.z = y0.z + dB[2]; o.w = y0.w + dB[3];
    *(float4*)(out + zoB) = o;
    o.x = y1.x + dB[4]; o.y = y1.y + dB[5]; o.z = y1.z + dB[6]; o.w = y1.w + dB[7];
    *(float4*)(out + zoB + 4) = o;

    double s = 0.0;
#pragma unroll
    for (int i = 0; i < 8; i++) s += (double)dA[i] * dA[i] + (double)dB[i] * dB[i];
#pragma unroll
    for (int off = 16; off > 0; off >>= 1)
        s += __shfl_down_sync(0xffffffffu, s, off);

    __shared__ double sp[8];
    if (lane == 0) sp[w] = s;
    __syncthreads();
    if (tid == 0) {
        double t = 0.0;
#pragma unroll
        for (int i = 0; i < 8; i++) t += sp[i];
        g_part[blockIdx.x] = t;
    }
}

__global__ void k_final(float* __restrict__ out) {
    __shared__ double red[256];
    int tid = threadIdx.x;
    double s = 0.0;
    for (int i = tid; i < NPART; i += 256) s += g_part[i];
    red[tid] = s;
    __syncthreads();
    for (int st = 128; st > 0; st >>= 1) {
        if (tid < st) red[tid] += red[tid + st];
        __syncthreads();
    }
    if (tid == 0) {
        float m = (float)(red[0] / (double)ZQN);
        out[LOSS_OFF] = m + 0.25f * m;
    }
    for (int i = tid; i < NROWS; i += 256) out[IDX_OFF + i] = (float)g_idx[i];
}

// ===========================================================================
extern "C" void kernel_launch(void* const* d_in, const int* in_sizes, int n_in,
                              void* d_out, int out_size) {
    const float* z = (const float*)d_in[0];
    const float* emb = (const float*)d_in[1];
    float* out = (float*)d_out;

    k_se<<<16, 128>>>(emb);
    k_sz<<<128, 256>>>(z);
    k_cvt<<<128, 256>>>(emb);

    cudaFuncSetAttribute(k_filter, cudaFuncAttributeMaxDynamicSharedMemorySize, SMEM_F);
    k_filter<<<256, 256, SMEM_F>>>(z);

    k_rescore<<<4096, 256>>>(z, emb);
    k_gather<<<2048, 256>>>(z, emb, out);
    k_final<<<1, 256>>>(out);
}

// round 11
// speedup vs baseline: 1.0111x; 1.0111x over previous
#include <cuda_runtime.h>
#include <cuda_bf16.h>
#include <cstdint>

#define NROWS   32768
#define KCODES  2048
#define CDIM    256
#define ZQN     8388608
#define LOSS_OFF 8388608
#define IDX_OFF  8388609
#define NPART   2048
#define CAND_MAX 32
#define FILT_EPS 2.5e-3f

// B tile row stride in bf16 (256 data + 8 pad; 528B = 33*16; 528 % 128 = 16 -> conflict-free)
#define RS 264

// ---- scratch (device globals; no allocation allowed) ----------------------
__device__ float          g_se[KCODES];
__device__ float          g_sz[NROWS];
__device__ int            g_idx[NROWS];
__device__ double         g_part[NPART];
__device__ __nv_bfloat16  g_embh[KCODES * RS];   // emb in bf16, padded rows
__device__ int            g_cnt[NROWS];
__device__ int            g_cand[NROWS * CAND_MAX];

// ---- helpers ---------------------------------------------------------------
__device__ __forceinline__ uint32_t smem_u32(const void* p) {
    uint32_t a;
    asm("{ .reg .u64 t; cvta.to.shared.u64 t, %1; cvt.u32.u64 %0, t; }"
        : "=r"(a) : "l"(p));
    return a;
}
__device__ __forceinline__ void cp16(uint32_t dst, const void* src) {
    asm volatile("cp.async.cg.shared.global [%0], [%1], 16;"
                 :: "r"(dst), "l"(src) : "memory");
}
#define CP_COMMIT() asm volatile("cp.async.commit_group;" ::: "memory")
#define CP_WAIT1()  asm volatile("cp.async.wait_group 1;" ::: "memory")
#define CP_WAIT0()  asm volatile("cp.async.wait_group 0;" ::: "memory")

// bf16 warp MMA m16n8k16 (Ampere-era PTX; valid on plain sm_103 target)
__device__ __forceinline__ void mma16816(float* d, const uint32_t* a, const uint32_t* b) {
    asm volatile(
        "mma.sync.aligned.m16n8k16.row.col.f32.bf16.bf16.f32 "
        "{%0,%1,%2,%3}, {%4,%5,%6,%7}, {%8,%9}, {%0,%1,%2,%3};"
        : "+f"(d[0]), "+f"(d[1]), "+f"(d[2]), "+f"(d[3])
        : "r"(a[0]), "r"(a[1]), "r"(a[2]), "r"(a[3]), "r"(b[0]), "r"(b[1]));
}
// ldmatrix x4: 4 8x8 b16 tiles, tile j addressed by lane group j*8..j*8+7
__device__ __forceinline__ void ldm4(uint32_t* r, uint32_t a) {
    asm volatile("ldmatrix.sync.aligned.m8n8.x4.shared.b16 {%0,%1,%2,%3}, [%4];"
        : "=r"(r[0]), "=r"(r[1]), "=r"(r[2]), "=r"(r[3]) : "r"(a));
}

// ---- smem layout for k_filter (bytes) --------------------------------------
#define SA    0                 // A: 128 x RS bf16                    67584
#define SB    67584             // B: 2 x (128 x RS) bf16             135168
#define SSE   202752            // se staging [2][128] f32              1024
#define SRM   203776            // rowmin [128][4] f32                  2048
#define SCAND 205824            // candidates [128][32] int            16384
#define SCNT  222208            // counts [128] int                      512
#define SMEM_F 222720
#define BUFE  (128 * RS)        // bf16 elems per B buffer

// ===========================================================================
// per-code / per-row squared norms (exact fp32, same sequences as R1)
// ===========================================================================
__global__ void k_se(const float* __restrict__ emb) {
    int k = blockIdx.x * 128 + threadIdx.x;
    const float4* e = (const float4*)(emb + (size_t)k * CDIM);
    float s = 0.f;
#pragma unroll 8
    for (int i = 0; i < CDIM / 4; i++) {
        float4 v = e[i];
        s += v.x * v.x; s += v.y * v.y; s += v.z * v.z; s += v.w * v.w;
    }
    g_se[k] = s;
}

__global__ void k_sz(const float* __restrict__ z) {
    int n = blockIdx.x * 256 + threadIdx.x;
    int b = n >> 12, s = n & 4095;
    const float* p = z + (size_t)b * 1048576 + s;
    float acc = 0.f;
#pragma unroll 8
    for (int c = 0; c < CDIM; c++) {
        float v = p[(size_t)c * 4096];
        acc += v * v;
    }
    g_sz[n] = acc;
}

// emb fp32 -> bf16 into padded [code][RS] layout
__global__ void k_cvt(const float* __restrict__ emb) {
    int g = blockIdx.x * 256 + threadIdx.x;       // 32768 groups of 16 elems
    int code = g >> 4, m = g & 15;
    const float4* src = (const float4*)(emb + (size_t)code * CDIM + m * 16);
    __nv_bfloat162 v[8];
#pragma unroll
    for (int i = 0; i < 4; i++) {
        float4 f = src[i];
        v[2 * i]     = __floats2bfloat162_rn(f.x, f.y);
        v[2 * i + 1] = __floats2bfloat162_rn(f.z, f.w);
    }
    __nv_bfloat162* dst = (__nv_bfloat162*)(g_embh + (size_t)code * RS + m * 16);
#pragma unroll
    for (int i = 0; i < 8; i++) dst[i] = v[i];
}

// ===========================================================================
// Warp-MMA bf16 distance filter. 256 CTAs x 128 rows x 2048 codes.
// Fragments loaded via ldmatrix.x4 (A: 4/ks, B: 2/ks) — mapping verified
// identical to the R10 scalar-LDS layout.
// ===========================================================================
__global__ __launch_bounds__(256, 1) void k_filter(const float* __restrict__ z) {
    extern __shared__ char smem[];
    __nv_bfloat16* As   = (__nv_bfloat16*)(smem + SA);
    float*         se_s = (float*)(smem + SSE);
    float*         rowm = (float*)(smem + SRM);
    int*           scand = (int*)(smem + SCAND);
    int*           scnt  = (int*)(smem + SCNT);
    const uint32_t sbase = smem_u32(smem);

    const int tid = threadIdx.x, lane = tid & 31, wid = tid >> 5;
    const int qr = lane >> 2, qc = lane & 3;
    const int WM = wid & 1, WN = wid >> 1;          // 2 x 4 warp grid
    const int n0 = blockIdx.x * 128;

    // ---- A fill: z rows n0..n0+127 -> bf16 As[row][c] (coalesced over row)
    {
        const float* zb = z + ((size_t)(n0 >> 12)) * 1048576 + (n0 & 4095);
#pragma unroll 8
        for (int i = 0; i < 128; i++) {
            int u = tid + i * 256;                  // 0..32767
            int row = u & 127, c = u >> 7;
            As[row * RS + c] = __float2bfloat16(zb[(size_t)c * 4096 + row]);
        }
    }
    if (tid < 128) scnt[tid] = 0;
    for (int i = tid; i < 512; i += 256) rowm[i] = 1e30f;

    // ---- ldmatrix per-lane base addresses ----
    const int l7 = lane & 7;
    // A: tile j: j=0 rows, j=1 rows+8, j=2 k+8, j=3 rows+8,k+8
    const int a_row  = 64 * WM + l7 + 8 * ((lane >> 3) & 1);
    const int a_koff = (lane >> 4) * 8;
    const uint32_t a_base =
        sbase + SA + (uint32_t)((a_row * RS + a_koff) * 2);
    // B (pair of nf): j=0 nf,k0; j=1 nf,k+8; j=2 nf+1,k0; j=3 nf+1,k+8
    const int bt = lane >> 3;
    const int b_rowoff = 8 * (bt >> 1) + l7;        // within nf-pair
    const int b_koff = 8 * (bt & 1);
    const uint32_t b_lane_off =
        (uint32_t)(((32 * WN + b_rowoff) * RS + b_koff) * 2);

    // ---- B tile async loader (16B chunk = 8 bf16 elements) ----
    auto issueB = [&](int t) {
        const __nv_bfloat16* src = g_embh + (size_t)t * 128 * RS;
        uint32_t dbase = sbase + SB + (t & 1) * (BUFE * 2);
#pragma unroll
        for (int i = 0; i < 16; i++) {
            int u = tid + i * 256;
            int n = u >> 5, m = u & 31;
            cp16(dbase + (uint32_t)(n * RS * 2 + m * 16),
                 (const void*)(src + (size_t)n * RS + m * 8));
        }
        if (tid < 128) se_s[(t & 1) * 128 + tid] = g_se[t * 128 + tid];
    };

    issueB(0);
    CP_COMMIT();

    for (int t = 0; t < 16; t++) {
        if (t < 15) { issueB(t + 1); CP_COMMIT(); CP_WAIT1(); }
        else        { CP_WAIT0(); }
        __syncthreads();

        const uint32_t bbuf = sbase + SB + (t & 1) * (BUFE * 2) + b_lane_off;
        float acc[4][4][4];
#pragma unroll
        for (int mf = 0; mf < 4; mf++)
#pragma unroll
            for (int nf = 0; nf < 4; nf++)
#pragma unroll
                for (int i = 0; i < 4; i++) acc[mf][nf][i] = 0.f;

#pragma unroll
        for (int ks = 0; ks < 16; ks++) {
            const uint32_t kb = (uint32_t)(ks * 32);   // 16 bf16 = 32 bytes
            uint32_t a[4][4], b[4][2];
#pragma unroll
            for (int mf = 0; mf < 4; mf++)
                ldm4(a[mf], a_base + (uint32_t)(16 * mf * RS * 2) + kb);
            {
                uint32_t bv[4];
                ldm4(bv, bbuf + kb);                       // nf 0,1
                b[0][0] = bv[0]; b[0][1] = bv[1];
                b[1][0] = bv[2]; b[1][1] = bv[3];
                ldm4(bv, bbuf + (uint32_t)(16 * RS * 2) + kb);  // nf 2,3
                b[2][0] = bv[0]; b[2][1] = bv[1];
                b[3][0] = bv[2]; b[3][1] = bv[3];
            }
#pragma unroll
            for (int mf = 0; mf < 4; mf++)
#pragma unroll
                for (int nf = 0; nf < 4; nf++)
                    mma16816(acc[mf][nf], a[mf], b[nf]);
        }

        // ---- per-row min fold (tt = se - 2*acc; sz omitted: row-constant)
        const float* sep = se_s + (t & 1) * 128;
        float rmin[4][2];
#pragma unroll
        for (int mf = 0; mf < 4; mf++) { rmin[mf][0] = 1e30f; rmin[mf][1] = 1e30f; }
#pragma unroll
        for (int mf = 0; mf < 4; mf++)
#pragma unroll
            for (int nf = 0; nf < 4; nf++) {
                int cb = 32 * WN + 8 * nf + 2 * qc;
                float s0 = sep[cb], s1 = sep[cb + 1];
                float t00 = fmaf(-2.f, acc[mf][nf][0], s0);
                float t01 = fmaf(-2.f, acc[mf][nf][1], s1);
                float t10 = fmaf(-2.f, acc[mf][nf][2], s0);
                float t11 = fmaf(-2.f, acc[mf][nf][3], s1);
                rmin[mf][0] = fminf(rmin[mf][0], fminf(t00, t01));
                rmin[mf][1] = fminf(rmin[mf][1], fminf(t10, t11));
            }
#pragma unroll
        for (int mf = 0; mf < 4; mf++)
#pragma unroll
            for (int h = 0; h < 2; h++) {
                float v = rmin[mf][h];
                v = fminf(v, __shfl_xor_sync(0xffffffffu, v, 1));
                v = fminf(v, __shfl_xor_sync(0xffffffffu, v, 2));
                if (qc == 0) {                      // exclusive (row, WN) owner
                    int r = 64 * WM + 16 * mf + qr + 8 * h;
                    float* p = &rowm[r * 4 + WN];
                    *p = fminf(*p, v);
                }
            }
        __syncthreads();

        // ---- emission pass (conservative superset vs running min)
#pragma unroll
        for (int mf = 0; mf < 4; mf++)
#pragma unroll
            for (int h = 0; h < 2; h++) {
                int r = 64 * WM + 16 * mf + qr + 8 * h;
                const float* rp = rowm + r * 4;
                float m4 = fminf(fminf(rp[0], rp[1]), fminf(rp[2], rp[3])) + FILT_EPS;
#pragma unroll
                for (int nf = 0; nf < 4; nf++) {
                    int cb = 32 * WN + 8 * nf + 2 * qc;
                    float t0 = fmaf(-2.f, acc[mf][nf][2 * h],     sep[cb]);
                    float t1 = fmaf(-2.f, acc[mf][nf][2 * h + 1], sep[cb + 1]);
                    if (t0 < m4) {
                        int p = atomicAdd(&scnt[r], 1);
                        if (p < CAND_MAX) scand[r * CAND_MAX + p] = t * 128 + cb;
                    }
                    if (t1 < m4) {
                        int p = atomicAdd(&scnt[r], 1);
                        if (p < CAND_MAX) scand[r * CAND_MAX + p] = t * 128 + cb + 1;
                    }
                }
            }
        __syncthreads();
    }

    if (tid < 128) g_cnt[n0 + tid] = scnt[tid];
    for (int i = tid; i < 128 * CAND_MAX; i += 256)
        g_cand[(size_t)n0 * CAND_MAX + i] = scand[i];
}

// ===========================================================================
// Exact fp32 rescore — one WARP per row, 8 candidate slots x 4 redundant
// lanes (slot = lane&7). Redundant lanes load identical addresses, so each
// LDG touches only 8 distinct lines. Per-candidate math is the bit-exact R1
// sequence: serial c=0..255 fmaf, d=(sz+se)-2acc, lexicographic (d,k) min.
// ===========================================================================
__global__ __launch_bounds__(256) void k_rescore(const float* __restrict__ z,
                                                 const float* __restrict__ emb) {
    __shared__ float zrow[8][256];
    const int tid = threadIdx.x, w = tid >> 5, lane = tid & 31;
    const int n0 = blockIdx.x * 8;
    const int bb = n0 >> 12;
    const float* zb = z + (size_t)bb * 1048576 + (n0 & 4095);
    {
        int r = tid & 7, cp = tid >> 3;
#pragma unroll
        for (int jj = 0; jj < 8; jj++) {
            int c = cp + jj * 32;
            zrow[r][c] = zb[(size_t)c * 4096 + r];
        }
    }
    __syncthreads();

    const int n = n0 + w;
    const int cnt = g_cnt[n];
    const float sz = g_sz[n];
    const float* zr = zrow[w];
    float bd = 1e38f;
    int bi = 0x7fffffff;

    if (cnt <= CAND_MAX) {
        const int slot = lane & 7;
        for (int q0 = 0; q0 < cnt; q0 += 8) {
            int q = q0 + slot;
            bool valid = q < cnt;
            int k = g_cand[(size_t)n * CAND_MAX + (valid ? q : 0)];
            const float* e = emb + (size_t)k * 256;
            float acc = 0.f;
#pragma unroll 8
            for (int c = 0; c < 256; c++) acc = fmaf(zr[c], e[c], acc);
            float d = (sz + g_se[k]) - 2.0f * acc;
            if (!valid) { d = 1e38f; k = 0x7fffffff; }
            if (d < bd || (d == bd && k < bi)) { bd = d; bi = k; }
        }
    } else {
        // filter overflow (never expected): exact brute force over all codes
        for (int k = lane; k < KCODES; k += 32) {
            const float* e = emb + (size_t)k * 256;
            float acc = 0.f;
            for (int c = 0; c < 256; c++) acc = fmaf(zr[c], e[c], acc);
            float d = (sz + g_se[k]) - 2.0f * acc;
            if (d < bd || (d == bd && k < bi)) { bd = d; bi = k; }
        }
    }
#pragma unroll
    for (int off = 16; off > 0; off >>= 1) {
        float d2 = __shfl_down_sync(0xffffffffu, bd, off);
        int i2 = __shfl_down_sync(0xffffffffu, bi, off);
        if (d2 < bd || (d2 == bd && i2 < bi)) { bd = d2; bi = i2; }
    }
    if (lane == 0) g_idx[n] = bi;
}

// ===========================================================================
// gather + z_q_st + loss partials (2 rows per warp)
// ===========================================================================
__global__ __launch_bounds__(256) void k_gather(const float* __restrict__ z,
                                                const float* __restrict__ emb,
                                                float* __restrict__ out) {
    const int tid = threadIdx.x, lane = tid & 31, w = tid >> 5;
    const int n = blockIdx.x * 16 + w * 2;
    const int iA = g_idx[n], iB = g_idx[n + 1];
    const size_t eoA = (size_t)iA * 256 + lane * 8;
    const size_t eoB = (size_t)iB * 256 + lane * 8;
    const size_t zoA = (size_t)n * 256 + lane * 8;
    const size_t zoB = zoA + 256;

    float4 a0 = *(const float4*)(emb + eoA), a1 = *(const float4*)(emb + eoA + 4);
    float4 b0 = *(const float4*)(emb + eoB), b1 = *(const float4*)(emb + eoB + 4);
    float4 x0 = *(const float4*)(z + zoA),   x1 = *(const float4*)(z + zoA + 4);
    float4 y0 = *(const float4*)(z + zoB),   y1 = *(const float4*)(z + zoB + 4);

    float dA[8] = {a0.x - x0.x, a0.y - x0.y, a0.z - x0.z, a0.w - x0.w,
                   a1.x - x1.x, a1.y - x1.y, a1.z - x1.z, a1.w - x1.w};
    float dB[8] = {b0.x - y0.x, b0.y - y0.y, b0.z - y0.z, b0.w - y0.w,
                   b1.x - y1.x, b1.y - y1.y, b1.z - y1.z, b1.w - y1.w};

    float4 o;
    o.x = x0.x + dA[0]; o.y = x0.y + dA[1]; o.z = x0.z + dA[2]; o.w = x0.w + dA[3];
    *(float4*)(out + zoA) = o;
    o.x = x1.x + dA[4]; o.y = x1.y + dA[5]; o.z = x1.z + dA[6]; o.w = x1.w + dA[7];
    *(float4*)(out + zoA + 4) = o;
    o.x = y0.x + dB[0]; o.y = y0.y + dB[1]; o.z = y0.z + dB[2]; o.w = y0.w + dB[3];
    *(float4*)(out + zoB) = o;
    o.x = y1.x + dB[4]; o.y = y1.y + dB[5]; o.z = y1.z + dB[6]; o.w = y1.w + dB[7];
    *(float4*)(out + zoB + 4) = o;

    double s = 0.0;
#pragma unroll
    for (int i = 0; i < 8; i++) s += (double)dA[i] * dA[i] + (double)dB[i] * dB[i];
#pragma unroll
    for (int off = 16; off > 0; off >>= 1)
        s += __shfl_down_sync(0xffffffffu, s, off);

    __shared__ double sp[8];
    if (lane == 0) sp[w] = s;
    __syncthreads();
    if (tid == 0) {
        double t = 0.0;
#pragma unroll
        for (int i = 0; i < 8; i++) t += sp[i];
        g_part[blockIdx.x] = t;
    }
}

__global__ void k_final(float* __restrict__ out) {
    __shared__ double red[256];
    int tid = threadIdx.x;
    double s = 0.0;
    for (int i = tid; i < NPART; i += 256) s += g_part[i];
    red[tid] = s;
    __syncthreads();
    for (int st = 128; st > 0; st >>= 1) {
        if (tid < st) red[tid] += red[tid + st];
        __syncthreads();
    }
    if (tid == 0) {
        float m = (float)(red[0] / (double)ZQN);
        out[LOSS_OFF] = m + 0.25f * m;
    }
    for (int i = tid; i < NROWS; i += 256) out[IDX_OFF + i] = (float)g_idx[i];
}

// ===========================================================================
extern "C" void kernel_launch(void* const* d_in, const int* in_sizes, int n_in,
                              void* d_out, int out_size) {
    const float* z = (const float*)d_in[0];
    const float* emb = (const float*)d_in[1];
    float* out = (float*)d_out;

    k_se<<<16, 128>>>(emb);
    k_sz<<<128, 256>>>(z);
    k_cvt<<<128, 256>>>(emb);

    cudaFuncSetAttribute(k_filter, cudaFuncAttributeMaxDynamicSharedMemorySize, SMEM_F);
    k_filter<<<256, 256, SMEM_F>>>(z);

    k_rescore<<<4096, 256>>>(z, emb);
    k_gather<<<2048, 256>>>(z, emb, out);
    k_final<<<1, 256>>>(out);
}

// round 12
// speedup vs baseline: 2.4839x; 2.4566x over previous
#include <cuda_runtime.h>
#include <cuda_bf16.h>
#include <cstdint>

#define NROWS   32768
#define KCODES  2048
#define CDIM    256
#define ZQN     8388608
#define LOSS_OFF 8388608
#define IDX_OFF  8388609
#define NPART   2048
#define FILT_EPS 2.5e-3f

// B tile row stride in bf16 (256 data + 8 pad; 528B = 33*16; conflict-free frags)
#define RS 264

// ---- scratch (device globals; no allocation allowed) ----------------------
__device__ float          g_se[KCODES];
__device__ float          g_sz[NROWS];
__device__ int            g_idx[NROWS];
__device__ double         g_part[NPART];
__device__ __nv_bfloat16  g_embh[KCODES * RS];     // emb in bf16, padded rows
__device__ float          g_tt[(size_t)NROWS * KCODES];  // full bf16-score dump (256MB)

// ---- helpers ---------------------------------------------------------------
__device__ __forceinline__ uint32_t smem_u32(const void* p) {
    uint32_t a;
    asm("{ .reg .u64 t; cvta.to.shared.u64 t, %1; cvt.u32.u64 %0, t; }"
        : "=r"(a) : "l"(p));
    return a;
}
__device__ __forceinline__ void cp16(uint32_t dst, const void* src) {
    asm volatile("cp.async.cg.shared.global [%0], [%1], 16;"
                 :: "r"(dst), "l"(src) : "memory");
}
#define CP_COMMIT() asm volatile("cp.async.commit_group;" ::: "memory")
#define CP_WAIT1()  asm volatile("cp.async.wait_group 1;" ::: "memory")
#define CP_WAIT0()  asm volatile("cp.async.wait_group 0;" ::: "memory")

// bf16 warp MMA m16n8k16 (Ampere-era PTX; valid on plain sm_103 target)
__device__ __forceinline__ void mma16816(float* d, const uint32_t* a, const uint32_t* b) {
    asm volatile(
        "mma.sync.aligned.m16n8k16.row.col.f32.bf16.bf16.f32 "
        "{%0,%1,%2,%3}, {%4,%5,%6,%7}, {%8,%9}, {%0,%1,%2,%3};"
        : "+f"(d[0]), "+f"(d[1]), "+f"(d[2]), "+f"(d[3])
        : "r"(a[0]), "r"(a[1]), "r"(a[2]), "r"(a[3]), "r"(b[0]), "r"(b[1]));
}
__device__ __forceinline__ void ldm4(uint32_t* r, uint32_t a) {
    asm volatile("ldmatrix.sync.aligned.m8n8.x4.shared.b16 {%0,%1,%2,%3}, [%4];"
        : "=r"(r[0]), "=r"(r[1]), "=r"(r[2]), "=r"(r[3]) : "r"(a));
}

// ---- smem layout for k_filter (bytes) --------------------------------------
#define SA    0                 // A: 128 x RS bf16                    67584
#define SB    67584             // B: 2 x (128 x RS) bf16             135168
#define SSE   202752            // se staging [2][128] f32              1024
#define SMEM_F 203776
#define BUFE  (128 * RS)

// ===========================================================================
// per-code / per-row squared norms (exact fp32, same sequences as R1)
// ===========================================================================
__global__ void k_se(const float* __restrict__ emb) {
    int k = blockIdx.x * 128 + threadIdx.x;
    const float4* e = (const float4*)(emb + (size_t)k * CDIM);
    float s = 0.f;
#pragma unroll 8
    for (int i = 0; i < CDIM / 4; i++) {
        float4 v = e[i];
        s += v.x * v.x; s += v.y * v.y; s += v.z * v.z; s += v.w * v.w;
    }
    g_se[k] = s;
}

__global__ void k_sz(const float* __restrict__ z) {
    int n = blockIdx.x * 256 + threadIdx.x;
    int b = n >> 12, s = n & 4095;
    const float* p = z + (size_t)b * 1048576 + s;
    float acc = 0.f;
#pragma unroll 8
    for (int c = 0; c < CDIM; c++) {
        float v = p[(size_t)c * 4096];
        acc += v * v;
    }
    g_sz[n] = acc;
}

// emb fp32 -> bf16 into padded [code][RS] layout
__global__ void k_cvt(const float* __restrict__ emb) {
    int g = blockIdx.x * 256 + threadIdx.x;
    int code = g >> 4, m = g & 15;
    const float4* src = (const float4*)(emb + (size_t)code * CDIM + m * 16);
    __nv_bfloat162 v[8];
#pragma unroll
    for (int i = 0; i < 4; i++) {
        float4 f = src[i];
        v[2 * i]     = __floats2bfloat162_rn(f.x, f.y);
        v[2 * i + 1] = __floats2bfloat162_rn(f.z, f.w);
    }
    __nv_bfloat162* dst = (__nv_bfloat162*)(g_embh + (size_t)code * RS + m * 16);
#pragma unroll
    for (int i = 0; i < 8; i++) dst[i] = v[i];
}

// ===========================================================================
// Warp-MMA bf16 score kernel: computes tt = se - 2*dot for all (row, code)
// and dumps the full matrix to g_tt (sector-perfect float2 stores).
// No emission, no counts, no atomics.
// ===========================================================================
__global__ __launch_bounds__(256, 1) void k_filter(const float* __restrict__ z) {
    extern __shared__ char smem[];
    __nv_bfloat16* As   = (__nv_bfloat16*)(smem + SA);
    float*         se_s = (float*)(smem + SSE);
    const uint32_t sbase = smem_u32(smem);

    const int tid = threadIdx.x, lane = tid & 31, wid = tid >> 5;
    const int qr = lane >> 2, qc = lane & 3;
    const int WM = wid & 1, WN = wid >> 1;          // 2 x 4 warp grid
    const int n0 = blockIdx.x * 128;

    // ---- A fill: z rows n0..n0+127 -> bf16 As[row][c]
    {
        const float* zb = z + ((size_t)(n0 >> 12)) * 1048576 + (n0 & 4095);
#pragma unroll 8
        for (int i = 0; i < 128; i++) {
            int u = tid + i * 256;
            int row = u & 127, c = u >> 7;
            As[row * RS + c] = __float2bfloat16(zb[(size_t)c * 4096 + row]);
        }
    }

    // ---- ldmatrix per-lane base addresses ----
    const int l7 = lane & 7;
    const int a_row  = 64 * WM + l7 + 8 * ((lane >> 3) & 1);
    const int a_koff = (lane >> 4) * 8;
    const uint32_t a_base = sbase + SA + (uint32_t)((a_row * RS + a_koff) * 2);
    const int bt = lane >> 3;
    const int b_rowoff = 8 * (bt >> 1) + l7;
    const int b_koff = 8 * (bt & 1);
    const uint32_t b_lane_off = (uint32_t)(((32 * WN + b_rowoff) * RS + b_koff) * 2);

    // ---- B tile async loader ----
    auto issueB = [&](int t) {
        const __nv_bfloat16* src = g_embh + (size_t)t * 128 * RS;
        uint32_t dbase = sbase + SB + (t & 1) * (BUFE * 2);
#pragma unroll
        for (int i = 0; i < 16; i++) {
            int u = tid + i * 256;
            int n = u >> 5, m = u & 31;
            cp16(dbase + (uint32_t)(n * RS * 2 + m * 16),
                 (const void*)(src + (size_t)n * RS + m * 8));
        }
        if (tid < 128) se_s[(t & 1) * 128 + tid] = g_se[t * 128 + tid];
    };

    issueB(0);
    CP_COMMIT();

    for (int t = 0; t < 16; t++) {
        if (t < 15) { issueB(t + 1); CP_COMMIT(); CP_WAIT1(); }
        else        { CP_WAIT0(); }
        __syncthreads();                            // tile t data visible

        const uint32_t bbuf = sbase + SB + (t & 1) * (BUFE * 2) + b_lane_off;
        float acc[4][4][4];
#pragma unroll
        for (int mf = 0; mf < 4; mf++)
#pragma unroll
            for (int nf = 0; nf < 4; nf++)
#pragma unroll
                for (int i = 0; i < 4; i++) acc[mf][nf][i] = 0.f;

#pragma unroll
        for (int ks = 0; ks < 16; ks++) {
            const uint32_t kb = (uint32_t)(ks * 32);
            uint32_t a[4][4], b[4][2];
#pragma unroll
            for (int mf = 0; mf < 4; mf++)
                ldm4(a[mf], a_base + (uint32_t)(16 * mf * RS * 2) + kb);
            {
                uint32_t bv[4];
                ldm4(bv, bbuf + kb);
                b[0][0] = bv[0]; b[0][1] = bv[1];
                b[1][0] = bv[2]; b[1][1] = bv[3];
                ldm4(bv, bbuf + (uint32_t)(16 * RS * 2) + kb);
                b[2][0] = bv[0]; b[2][1] = bv[1];
                b[3][0] = bv[2]; b[3][1] = bv[3];
            }
#pragma unroll
            for (int mf = 0; mf < 4; mf++)
#pragma unroll
                for (int nf = 0; nf < 4; nf++)
                    mma16816(acc[mf][nf], a[mf], b[nf]);
        }

        // ---- dump tt = se - 2*acc (float2 stores; 8 rows x 32B sectors/instr)
        const float* sep = se_s + (t & 1) * 128;
#pragma unroll
        for (int mf = 0; mf < 4; mf++) {
            const int r0 = n0 + 64 * WM + 16 * mf + qr;
#pragma unroll
            for (int nf = 0; nf < 4; nf++) {
                const int cb = 32 * WN + 8 * nf + 2 * qc;
                const float s0 = sep[cb], s1 = sep[cb + 1];
                const size_t col = (size_t)(t * 128 + cb);
                float2 v;
                v.x = fmaf(-2.f, acc[mf][nf][0], s0);
                v.y = fmaf(-2.f, acc[mf][nf][1], s1);
                *(float2*)(g_tt + ((size_t)r0 << 11) + col) = v;
                v.x = fmaf(-2.f, acc[mf][nf][2], s0);
                v.y = fmaf(-2.f, acc[mf][nf][3], s1);
                *(float2*)(g_tt + ((size_t)(r0 + 8) << 11) + col) = v;
            }
        }
        __syncthreads();    // all reads of buf done before issueB overwrites it
    }
}

// ===========================================================================
// Fused scan + exact rescore. One warp per row:
//  - stream the 2048 tt values (64 regs/lane, fully coalesced)
//  - warp-reduce the TRUE global min
//  - candidates: tt <= min + eps  (typically 1-2; min itself always included)
//  - exact fp32 rescore per hit: bit-exact R1 sequence (serial c=0..255 fmaf,
//    d=(sz+se)-2acc), lexicographic (d,k) warp reduce.
// No overflow path exists.
// ===========================================================================
__global__ __launch_bounds__(256) void k_scan(const float* __restrict__ z,
                                              const float* __restrict__ emb) {
    __shared__ float zrow[8][256];
    const int tid = threadIdx.x, w = tid >> 5, lane = tid & 31;
    const int n0 = blockIdx.x * 8;
    const int bb = n0 >> 12;
    const float* zb = z + (size_t)bb * 1048576 + (n0 & 4095);
    {
        int r = tid & 7, cp = tid >> 3;
#pragma unroll
        for (int jj = 0; jj < 8; jj++) {
            int c = cp + jj * 32;
            zrow[r][c] = zb[(size_t)c * 4096 + r];
        }
    }
    __syncthreads();

    const int n = n0 + w;
    const float sz = g_sz[n];
    const float* zr = zrow[w];
    const float* tp = g_tt + ((size_t)n << 11) + lane;

    float tl[64];
#pragma unroll
    for (int j = 0; j < 64; j++) tl[j] = tp[32 * j];

    float mn = tl[0];
#pragma unroll
    for (int j = 1; j < 64; j++) mn = fminf(mn, tl[j]);
#pragma unroll
    for (int off = 16; off > 0; off >>= 1)
        mn = fminf(mn, __shfl_xor_sync(0xffffffffu, mn, off));

    const float thr = mn + FILT_EPS;
    unsigned long long mask = 0ull;
#pragma unroll
    for (int j = 0; j < 64; j++)
        if (tl[j] <= thr) mask |= (1ull << j);

    float bd = 1e38f;
    int bi = 0x7fffffff;
    while (mask) {
        int j = __ffsll((long long)mask) - 1;
        mask &= mask - 1;
        int k = lane + 32 * j;
        const float* e = emb + (size_t)k * 256;
        float acc = 0.f;
#pragma unroll 8
        for (int c = 0; c < 256; c++) acc = fmaf(zr[c], e[c], acc);
        float d = (sz + g_se[k]) - 2.0f * acc;
        if (d < bd || (d == bd && k < bi)) { bd = d; bi = k; }
    }
#pragma unroll
    for (int off = 16; off > 0; off >>= 1) {
        float d2 = __shfl_down_sync(0xffffffffu, bd, off);
        int i2 = __shfl_down_sync(0xffffffffu, bi, off);
        if (d2 < bd || (d2 == bd && i2 < bi)) { bd = d2; bi = i2; }
    }
    if (lane == 0) g_idx[n] = bi;
}

// ===========================================================================
// gather + z_q_st + loss partials (2 rows per warp)
// ===========================================================================
__global__ __launch_bounds__(256) void k_gather(const float* __restrict__ z,
                                                const float* __restrict__ emb,
                                                float* __restrict__ out) {
    const int tid = threadIdx.x, lane = tid & 31, w = tid >> 5;
    const int n = blockIdx.x * 16 + w * 2;
    const int iA = g_idx[n], iB = g_idx[n + 1];
    const size_t eoA = (size_t)iA * 256 + lane * 8;
    const size_t eoB = (size_t)iB * 256 + lane * 8;
    const size_t zoA = (size_t)n * 256 + lane * 8;
    const size_t zoB = zoA + 256;

    float4 a0 = *(const float4*)(emb + eoA), a1 = *(const float4*)(emb + eoA + 4);
    float4 b0 = *(const float4*)(emb + eoB), b1 = *(const float4*)(emb + eoB + 4);
    float4 x0 = *(const float4*)(z + zoA),   x1 = *(const float4*)(z + zoA + 4);
    float4 y0 = *(const float4*)(z + zoB),   y1 = *(const float4*)(z + zoB + 4);

    float dA[8] = {a0.x - x0.x, a0.y - x0.y, a0.z - x0.z, a0.w - x0.w,
                   a1.x - x1.x, a1.y - x1.y, a1.z - x1.z, a1.w - x1.w};
    float dB[8] = {b0.x - y0.x, b0.y - y0.y, b0.z - y0.z, b0.w - y0.w,
                   b1.x - y1.x, b1.y - y1.y, b1.z - y1.z, b1.w - y1.w};

    float4 o;
    o.x = x0.x + dA[0]; o.y = x0.y + dA[1]; o.z = x0.z + dA[2]; o.w = x0.w + dA[3];
    *(float4*)(out + zoA) = o;
    o.x = x1.x + dA[4]; o.y = x1.y + dA[5]; o.z = x1.z + dA[6]; o.w = x1.w + dA[7];
    *(float4*)(out + zoA + 4) = o;
    o.x = y0.x + dB[0]; o.y = y0.y + dB[1]; o.z = y0.z + dB[2]; o.w = y0.w + dB[3];
    *(float4*)(out + zoB) = o;
    o.x = y1.x + dB[4]; o.y = y1.y + dB[5]; o.z = y1.z + dB[6]; o.w = y1.w + dB[7];
    *(float4*)(out + zoB + 4) = o;

    double s = 0.0;
#pragma unroll
    for (int i = 0; i < 8; i++) s += (double)dA[i] * dA[i] + (double)dB[i] * dB[i];
#pragma unroll
    for (int off = 16; off > 0; off >>= 1)
        s += __shfl_down_sync(0xffffffffu, s, off);

    __shared__ double sp[8];
    if (lane == 0) sp[w] = s;
    __syncthreads();
    if (tid == 0) {
        double t = 0.0;
#pragma unroll
        for (int i = 0; i < 8; i++) t += sp[i];
        g_part[blockIdx.x] = t;
    }
}

__global__ void k_final(float* __restrict__ out) {
    __shared__ double red[256];
    int tid = threadIdx.x;
    double s = 0.0;
    for (int i = tid; i < NPART; i += 256) s += g_part[i];
    red[tid] = s;
    __syncthreads();
    for (int st = 128; st > 0; st >>= 1) {
        if (tid < st) red[tid] += red[tid + st];
        __syncthreads();
    }
    if (tid == 0) {
        float m = (float)(red[0] / (double)ZQN);
        out[LOSS_OFF] = m + 0.25f * m;
    }
    for (int i = tid; i < NROWS; i += 256) out[IDX_OFF + i] = (float)g_idx[i];
}

// ===========================================================================
extern "C" void kernel_launch(void* const* d_in, const int* in_sizes, int n_in,
                              void* d_out, int out_size) {
    const float* z = (const float*)d_in[0];
    const float* emb = (const float*)d_in[1];
    float* out = (float*)d_out;

    k_se<<<16, 128>>>(emb);
    k_sz<<<128, 256>>>(z);
    k_cvt<<<128, 256>>>(emb);

    cudaFuncSetAttribute(k_filter, cudaFuncAttributeMaxDynamicSharedMemorySize, SMEM_F);
    k_filter<<<256, 256, SMEM_F>>>(z);

    k_scan<<<4096, 256>>>(z, emb);
    k_gather<<<2048, 256>>>(z, emb, out);
    k_final<<<1, 256>>>(out);
}

// round 13
// speedup vs baseline: 2.6422x; 1.0637x over previous
#include <cuda_runtime.h>
#include <cuda_bf16.h>
#include <cuda_fp16.h>
#include <cstdint>

#define NROWS   32768
#define KCODES  2048
#define CDIM    256
#define ZQN     8388608
#define LOSS_OFF 8388608
#define IDX_OFF  8388609
#define NPART   2048
#define FILT_EPS 2.5e-3f

// B tile row stride in bf16 (256 data + 8 pad; 528B = 33*16; conflict-free frags)
#define RS 264

// ---- scratch (device globals; no allocation allowed) ----------------------
__device__ float          g_se[KCODES];
__device__ float          g_sz[NROWS];
__device__ int            g_idx[NROWS];
__device__ double         g_part[NPART];
__device__ __nv_bfloat16  g_embh[KCODES * RS];          // emb in bf16, padded rows
__device__ __half         g_tth[(size_t)NROWS * KCODES]; // fp16 score dump (128MB)

// ---- helpers ---------------------------------------------------------------
__device__ __forceinline__ uint32_t smem_u32(const void* p) {
    uint32_t a;
    asm("{ .reg .u64 t; cvta.to.shared.u64 t, %1; cvt.u32.u64 %0, t; }"
        : "=r"(a) : "l"(p));
    return a;
}
__device__ __forceinline__ void cp16(uint32_t dst, const void* src) {
    asm volatile("cp.async.cg.shared.global [%0], [%1], 16;"
                 :: "r"(dst), "l"(src) : "memory");
}
#define CP_COMMIT() asm volatile("cp.async.commit_group;" ::: "memory")
#define CP_WAIT1()  asm volatile("cp.async.wait_group 1;" ::: "memory")
#define CP_WAIT0()  asm volatile("cp.async.wait_group 0;" ::: "memory")

// bf16 warp MMA m16n8k16 (Ampere-era PTX; valid on plain sm_103 target)
__device__ __forceinline__ void mma16816(float* d, const uint32_t* a, const uint32_t* b) {
    asm volatile(
        "mma.sync.aligned.m16n8k16.row.col.f32.bf16.bf16.f32 "
        "{%0,%1,%2,%3}, {%4,%5,%6,%7}, {%8,%9}, {%0,%1,%2,%3};"
        : "+f"(d[0]), "+f"(d[1]), "+f"(d[2]), "+f"(d[3])
        : "r"(a[0]), "r"(a[1]), "r"(a[2]), "r"(a[3]), "r"(b[0]), "r"(b[1]));
}
__device__ __forceinline__ void ldm4(uint32_t* r, uint32_t a) {
    asm volatile("ldmatrix.sync.aligned.m8n8.x4.shared.b16 {%0,%1,%2,%3}, [%4];"
        : "=r"(r[0]), "=r"(r[1]), "=r"(r[2]), "=r"(r[3]) : "r"(a));
}

// ---- smem layout for k_filter (bytes) --------------------------------------
#define SA    0                 // A: 128 x RS bf16                    67584
#define SB    67584             // B: 2 x (128 x RS) bf16             135168
#define SSE   202752            // se staging [2][128] f32              1024
#define SMEM_F 203776
#define BUFE  (128 * RS)

// ===========================================================================
// per-code / per-row squared norms (exact fp32, same sequences as R1)
// ===========================================================================
__global__ void k_se(const float* __restrict__ emb) {
    int k = blockIdx.x * 128 + threadIdx.x;
    const float4* e = (const float4*)(emb + (size_t)k * CDIM);
    float s = 0.f;
#pragma unroll 8
    for (int i = 0; i < CDIM / 4; i++) {
        float4 v = e[i];
        s += v.x * v.x; s += v.y * v.y; s += v.z * v.z; s += v.w * v.w;
    }
    g_se[k] = s;
}

__global__ void k_sz(const float* __restrict__ z) {
    int n = blockIdx.x * 256 + threadIdx.x;
    int b = n >> 12, s = n & 4095;
    const float* p = z + (size_t)b * 1048576 + s;
    float acc = 0.f;
#pragma unroll 8
    for (int c = 0; c < CDIM; c++) {
        float v = p[(size_t)c * 4096];
        acc += v * v;
    }
    g_sz[n] = acc;
}

// emb fp32 -> bf16 into padded [code][RS] layout
__global__ void k_cvt(const float* __restrict__ emb) {
    int g = blockIdx.x * 256 + threadIdx.x;
    int code = g >> 4, m = g & 15;
    const float4* src = (const float4*)(emb + (size_t)code * CDIM + m * 16);
    __nv_bfloat162 v[8];
#pragma unroll
    for (int i = 0; i < 4; i++) {
        float4 f = src[i];
        v[2 * i]     = __floats2bfloat162_rn(f.x, f.y);
        v[2 * i + 1] = __floats2bfloat162_rn(f.z, f.w);
    }
    __nv_bfloat162* dst = (__nv_bfloat162*)(g_embh + (size_t)code * RS + m * 16);
#pragma unroll
    for (int i = 0; i < 8; i++) dst[i] = v[i];
}

// ===========================================================================
// Warp-MMA bf16 score kernel: tt = se - 2*dot for all (row, code), dumped
// as fp16 to g_tth (half2 stores; 16B contiguous per quad per row).
// ===========================================================================
__global__ __launch_bounds__(256, 1) void k_filter(const float* __restrict__ z) {
    extern __shared__ char smem[];
    __nv_bfloat16* As   = (__nv_bfloat16*)(smem + SA);
    float*         se_s = (float*)(smem + SSE);
    const uint32_t sbase = smem_u32(smem);

    const int tid = threadIdx.x, lane = tid & 31, wid = tid >> 5;
    const int qr = lane >> 2, qc = lane & 3;
    const int WM = wid & 1, WN = wid >> 1;          // 2 x 4 warp grid
    const int n0 = blockIdx.x * 128;

    // ---- A fill: z rows n0..n0+127 -> bf16 As[row][c]
    {
        const float* zb = z + ((size_t)(n0 >> 12)) * 1048576 + (n0 & 4095);
#pragma unroll 8
        for (int i = 0; i < 128; i++) {
            int u = tid + i * 256;
            int row = u & 127, c = u >> 7;
            As[row * RS + c] = __float2bfloat16(zb[(size_t)c * 4096 + row]);
        }
    }

    // ---- ldmatrix per-lane base addresses ----
    const int l7 = lane & 7;
    const int a_row  = 64 * WM + l7 + 8 * ((lane >> 3) & 1);
    const int a_koff = (lane >> 4) * 8;
    const uint32_t a_base = sbase + SA + (uint32_t)((a_row * RS + a_koff) * 2);
    const int bt = lane >> 3;
    const int b_rowoff = 8 * (bt >> 1) + l7;
    const int b_koff = 8 * (bt & 1);
    const uint32_t b_lane_off = (uint32_t)(((32 * WN + b_rowoff) * RS + b_koff) * 2);

    // ---- B tile async loader ----
    auto issueB = [&](int t) {
        const __nv_bfloat16* src = g_embh + (size_t)t * 128 * RS;
        uint32_t dbase = sbase + SB + (t & 1) * (BUFE * 2);
#pragma unroll
        for (int i = 0; i < 16; i++) {
            int u = tid + i * 256;
            int n = u >> 5, m = u & 31;
            cp16(dbase + (uint32_t)(n * RS * 2 + m * 16),
                 (const void*)(src + (size_t)n * RS + m * 8));
        }
        if (tid < 128) se_s[(t & 1) * 128 + tid] = g_se[t * 128 + tid];
    };

    issueB(0);
    CP_COMMIT();

    for (int t = 0; t < 16; t++) {
        if (t < 15) { issueB(t + 1); CP_COMMIT(); CP_WAIT1(); }
        else        { CP_WAIT0(); }
        __syncthreads();                            // tile t data visible

        const uint32_t bbuf = sbase + SB + (t & 1) * (BUFE * 2) + b_lane_off;
        float acc[4][4][4];
#pragma unroll
        for (int mf = 0; mf < 4; mf++)
#pragma unroll
            for (int nf = 0; nf < 4; nf++)
#pragma unroll
                for (int i = 0; i < 4; i++) acc[mf][nf][i] = 0.f;

#pragma unroll
        for (int ks = 0; ks < 16; ks++) {
            const uint32_t kb = (uint32_t)(ks * 32);
            uint32_t a[4][4], b[4][2];
#pragma unroll
            for (int mf = 0; mf < 4; mf++)
                ldm4(a[mf], a_base + (uint32_t)(16 * mf * RS * 2) + kb);
            {
                uint32_t bv[4];
                ldm4(bv, bbuf + kb);
                b[0][0] = bv[0]; b[0][1] = bv[1];
                b[1][0] = bv[2]; b[1][1] = bv[3];
                ldm4(bv, bbuf + (uint32_t)(16 * RS * 2) + kb);
                b[2][0] = bv[0]; b[2][1] = bv[1];
                b[3][0] = bv[2]; b[3][1] = bv[3];
            }
#pragma unroll
            for (int mf = 0; mf < 4; mf++)
#pragma unroll
                for (int nf = 0; nf < 4; nf++)
                    mma16816(acc[mf][nf], a[mf], b[nf]);
        }

        // ---- dump tt = se - 2*acc as fp16 (half2 = 4B per lane per row)
        const float* sep = se_s + (t & 1) * 128;
#pragma unroll
        for (int mf = 0; mf < 4; mf++) {
            const int r0 = n0 + 64 * WM + 16 * mf + qr;
#pragma unroll
            for (int nf = 0; nf < 4; nf++) {
                const int cb = 32 * WN + 8 * nf + 2 * qc;
                const float s0 = sep[cb], s1 = sep[cb + 1];
                const size_t col = (size_t)(t * 128 + cb);
                float2 v;
                v.x = fmaf(-2.f, acc[mf][nf][0], s0);
                v.y = fmaf(-2.f, acc[mf][nf][1], s1);
                *(__half2*)(g_tth + ((size_t)r0 << 11) + col) = __float22half2_rn(v);
                v.x = fmaf(-2.f, acc[mf][nf][2], s0);
                v.y = fmaf(-2.f, acc[mf][nf][3], s1);
                *(__half2*)(g_tth + ((size_t)(r0 + 8) << 11) + col) = __float22half2_rn(v);
            }
        }
        __syncthreads();    // all reads of buf done before issueB overwrites it
    }
}

// ===========================================================================
// Fused scan + exact rescore. One warp per row:
//  - stream 2048 fp16 tt values (4 cols/lane x 16 groups; 8B loads, 16 MLP)
//  - warp-reduce the TRUE global min
//  - candidates: tt <= min + eps (typically 1-2; min always included)
//  - exact fp32 rescore per hit: bit-exact R1 sequence, lexicographic reduce.
// ===========================================================================
__global__ __launch_bounds__(256) void k_scan(const float* __restrict__ z,
                                              const float* __restrict__ emb) {
    __shared__ float zrow[8][256];
    const int tid = threadIdx.x, w = tid >> 5, lane = tid & 31;
    const int n0 = blockIdx.x * 8;
    const int bb = n0 >> 12;
    const float* zb = z + (size_t)bb * 1048576 + (n0 & 4095);
    {
        int r = tid & 7, cp = tid >> 3;
#pragma unroll
        for (int jj = 0; jj < 8; jj++) {
            int c = cp + jj * 32;
            zrow[r][c] = zb[(size_t)c * 4096 + r];
        }
    }
    __syncthreads();

    const int n = n0 + w;
    const float sz = g_sz[n];
    const float* zr = zrow[w];
    const __half* tp = g_tth + ((size_t)n << 11) + 4 * lane;

    // lane covers cols 128*j + 4*lane + {0..3}, j = 0..15
    float tl[64];
#pragma unroll
    for (int j = 0; j < 16; j++) {
        __half2 p0 = *(const __half2*)(tp + 128 * j);
        __half2 p1 = *(const __half2*)(tp + 128 * j + 2);
        float2 f0 = __half22float2(p0);
        float2 f1 = __half22float2(p1);
        tl[4 * j] = f0.x; tl[4 * j + 1] = f0.y;
        tl[4 * j + 2] = f1.x; tl[4 * j + 3] = f1.y;
    }

    float mn = tl[0];
#pragma unroll
    for (int j = 1; j < 64; j++) mn = fminf(mn, tl[j]);
#pragma unroll
    for (int off = 16; off > 0; off >>= 1)
        mn = fminf(mn, __shfl_xor_sync(0xffffffffu, mn, off));

    const float thr = mn + FILT_EPS;
    unsigned long long mask = 0ull;
#pragma unroll
    for (int j = 0; j < 64; j++)
        if (tl[j] <= thr) mask |= (1ull << j);

    float bd = 1e38f;
    int bi = 0x7fffffff;
    while (mask) {
        int b = __ffsll((long long)mask) - 1;
        mask &= mask - 1;
        int k = 128 * (b >> 2) + 4 * lane + (b & 3);
        const float* e = emb + (size_t)k * 256;
        float acc = 0.f;
#pragma unroll 8
        for (int c = 0; c < 256; c++) acc = fmaf(zr[c], e[c], acc);
        float d = (sz + g_se[k]) - 2.0f * acc;
        if (d < bd || (d == bd && k < bi)) { bd = d; bi = k; }
    }
#pragma unroll
    for (int off = 16; off > 0; off >>= 1) {
        float d2 = __shfl_down_sync(0xffffffffu, bd, off);
        int i2 = __shfl_down_sync(0xffffffffu, bi, off);
        if (d2 < bd || (d2 == bd && i2 < bi)) { bd = d2; bi = i2; }
    }
    if (lane == 0) g_idx[n] = bi;
}

// ===========================================================================
// gather + z_q_st + loss partials (2 rows per warp)
// ===========================================================================
__global__ __launch_bounds__(256) void k_gather(const float* __restrict__ z,
                                                const float* __restrict__ emb,
                                                float* __restrict__ out) {
    const int tid = threadIdx.x, lane = tid & 31, w = tid >> 5;
    const int n = blockIdx.x * 16 + w * 2;
    const int iA = g_idx[n], iB = g_idx[n + 1];
    const size_t eoA = (size_t)iA * 256 + lane * 8;
    const size_t eoB = (size_t)iB * 256 + lane * 8;
    const size_t zoA = (size_t)n * 256 + lane * 8;
    const size_t zoB = zoA + 256;

    float4 a0 = *(const float4*)(emb + eoA), a1 = *(const float4*)(emb + eoA + 4);
    float4 b0 = *(const float4*)(emb + eoB), b1 = *(const float4*)(emb + eoB + 4);
    float4 x0 = *(const float4*)(z + zoA),   x1 = *(const float4*)(z + zoA + 4);
    float4 y0 = *(const float4*)(z + zoB),   y1 = *(const float4*)(z + zoB + 4);

    float dA[8] = {a0.x - x0.x, a0.y - x0.y, a0.z - x0.z, a0.w - x0.w,
                   a1.x - x1.x, a1.y - x1.y, a1.z - x1.z, a1.w - x1.w};
    float dB[8] = {b0.x - y0.x, b0.y - y0.y, b0.z - y0.z, b0.w - y0.w,
                   b1.x - y1.x, b1.y - y1.y, b1.z - y1.z, b1.w - y1.w};

    float4 o;
    o.x = x0.x + dA[0]; o.y = x0.y + dA[1]; o.z = x0.z + dA[2]; o.w = x0.w + dA[3];
    *(float4*)(out + zoA) = o;
    o.x = x1.x + dA[4]; o.y = x1.y + dA[5]; o.z = x1.z + dA[6]; o.w = x1.w + dA[7];
    *(float4*)(out + zoA + 4) = o;
    o.x = y0.x + dB[0]; o.y = y0.y + dB[1]; o.z = y0.z + dB[2]; o.w = y0.w + dB[3];
    *(float4*)(out + zoB) = o;
    o.x = y1.x + dB[4]; o.y = y1.y + dB[5]; o.z = y1.z + dB[6]; o.w = y1.w + dB[7];
    *(float4*)(out + zoB + 4) = o;

    double s = 0.0;
#pragma unroll
    for (int i = 0; i < 8; i++) s += (double)dA[i] * dA[i] + (double)dB[i] * dB[i];
#pragma unroll
    for (int off = 16; off > 0; off >>= 1)
        s += __shfl_down_sync(0xffffffffu, s, off);

    __shared__ double sp[8];
    if (lane == 0) sp[w] = s;
    __syncthreads();
    if (tid == 0) {
        double t = 0.0;
#pragma unroll
        for (int i = 0; i < 8; i++) t += sp[i];
        g_part[blockIdx.x] = t;
    }
}

__global__ void k_final(float* __restrict__ out) {
    __shared__ double red[256];
    int tid = threadIdx.x;
    double s = 0.0;
    for (int i = tid; i < NPART; i += 256) s += g_part[i];
    red[tid] = s;
    __syncthreads();
    for (int st = 128; st > 0; st >>= 1) {
        if (tid < st) red[tid] += red[tid + st];
        __syncthreads();
    }
    if (tid == 0) {
        float m = (float)(red[0] / (double)ZQN);
        out[LOSS_OFF] = m + 0.25f * m;
    }
    for (int i = tid; i < NROWS; i += 256) out[IDX_OFF + i] = (float)g_idx[i];
}

// ===========================================================================
extern "C" void kernel_launch(void* const* d_in, const int* in_sizes, int n_in,
                              void* d_out, int out_size) {
    const float* z = (const float*)d_in[0];
    const float* emb = (const float*)d_in[1];
    float* out = (float*)d_out;

    k_se<<<16, 128>>>(emb);
    k_sz<<<128, 256>>>(z);
    k_cvt<<<128, 256>>>(emb);

    cudaFuncSetAttribute(k_filter, cudaFuncAttributeMaxDynamicSharedMemorySize, SMEM_F);
    k_filter<<<256, 256, SMEM_F>>>(z);

    k_scan<<<4096, 256>>>(z, emb);
    k_gather<<<2048, 256>>>(z, emb, out);
    k_final<<<1, 256>>>(out);
}

// round 14
// speedup vs baseline: 3.1088x; 1.1766x over previous
#include <cuda_runtime.h>
#include <cuda_bf16.h>
#include <cuda_fp16.h>
#include <cstdint>

#define NROWS   32768
#define KCODES  2048
#define CDIM    256
#define ZQN     8388608
#define LOSS_OFF 8388608
#define IDX_OFF  8388609
#define NPART   2048
#define FILT_EPS 7.5e-4f

// B tile row stride in bf16 (256 data + 8 pad; 528B = 33*16; conflict-free frags)
#define RS 264

// ---- scratch (device globals; no allocation allowed) ----------------------
__device__ float          g_se[KCODES];
__device__ float          g_sz[NROWS];
__device__ int            g_idx[NROWS];
__device__ double         g_part[NPART];
__device__ __nv_bfloat16  g_embh[KCODES * RS];          // emb in bf16, padded rows
__device__ __half         g_tth[(size_t)NROWS * KCODES]; // fp16 score dump (128MB)

// ---- helpers ---------------------------------------------------------------
__device__ __forceinline__ uint32_t smem_u32(const void* p) {
    uint32_t a;
    asm("{ .reg .u64 t; cvta.to.shared.u64 t, %1; cvt.u32.u64 %0, t; }"
        : "=r"(a) : "l"(p));
    return a;
}
__device__ __forceinline__ void cp16(uint32_t dst, const void* src) {
    asm volatile("cp.async.cg.shared.global [%0], [%1], 16;"
                 :: "r"(dst), "l"(src) : "memory");
}
#define CP_COMMIT() asm volatile("cp.async.commit_group;" ::: "memory")
#define CP_WAIT1()  asm volatile("cp.async.wait_group 1;" ::: "memory")
#define CP_WAIT0()  asm volatile("cp.async.wait_group 0;" ::: "memory")

// bf16 warp MMA m16n8k16 (Ampere-era PTX; valid on plain sm_103 target)
__device__ __forceinline__ void mma16816(float* d, const uint32_t* a, const uint32_t* b) {
    asm volatile(
        "mma.sync.aligned.m16n8k16.row.col.f32.bf16.bf16.f32 "
        "{%0,%1,%2,%3}, {%4,%5,%6,%7}, {%8,%9}, {%0,%1,%2,%3};"
        : "+f"(d[0]), "+f"(d[1]), "+f"(d[2]), "+f"(d[3])
        : "r"(a[0]), "r"(a[1]), "r"(a[2]), "r"(a[3]), "r"(b[0]), "r"(b[1]));
}
__device__ __forceinline__ void ldm4(uint32_t* r, uint32_t a) {
    asm volatile("ldmatrix.sync.aligned.m8n8.x4.shared.b16 {%0,%1,%2,%3}, [%4];"
        : "=r"(r[0]), "=r"(r[1]), "=r"(r[2]), "=r"(r[3]) : "r"(a));
}

// ---- smem layout for k_filter (bytes) --------------------------------------
#define SA    0                 // A: 128 x RS bf16                    67584
#define SB    67584             // B: 2 x (128 x RS) bf16             135168
#define SSE   202752            // se staging [2][128] f32              1024
#define SMEM_F 203776
#define BUFE  (128 * RS)

// ===========================================================================
// per-code / per-row squared norms (exact fp32, same sequences as R1)
// ===========================================================================
__global__ void k_se(const float* __restrict__ emb) {
    int k = blockIdx.x * 128 + threadIdx.x;
    const float4* e = (const float4*)(emb + (size_t)k * CDIM);
    float s = 0.f;
#pragma unroll 8
    for (int i = 0; i < CDIM / 4; i++) {
        float4 v = e[i];
        s += v.x * v.x; s += v.y * v.y; s += v.z * v.z; s += v.w * v.w;
    }
    g_se[k] = s;
}

__global__ void k_sz(const float* __restrict__ z) {
    int n = blockIdx.x * 256 + threadIdx.x;
    int b = n >> 12, s = n & 4095;
    const float* p = z + (size_t)b * 1048576 + s;
    float acc = 0.f;
#pragma unroll 8
    for (int c = 0; c < CDIM; c++) {
        float v = p[(size_t)c * 4096];
        acc += v * v;
    }
    g_sz[n] = acc;
}

// emb fp32 -> bf16 into padded [code][RS] layout
__global__ void k_cvt(const float* __restrict__ emb) {
    int g = blockIdx.x * 256 + threadIdx.x;
    int code = g >> 4, m = g & 15;
    const float4* src = (const float4*)(emb + (size_t)code * CDIM + m * 16);
    __nv_bfloat162 v[8];
#pragma unroll
    for (int i = 0; i < 4; i++) {
        float4 f = src[i];
        v[2 * i]     = __floats2bfloat162_rn(f.x, f.y);
        v[2 * i + 1] = __floats2bfloat162_rn(f.z, f.w);
    }
    __nv_bfloat162* dst = (__nv_bfloat162*)(g_embh + (size_t)code * RS + m * 16);
#pragma unroll
    for (int i = 0; i < 8; i++) dst[i] = v[i];
}

// ===========================================================================
// Warp-MMA bf16 score kernel: tt = se - 2*dot for all (row, code), dumped
// as fp16 to g_tth (half2 stores; 16B contiguous per quad per row).
// ===========================================================================
__global__ __launch_bounds__(256, 1) void k_filter(const float* __restrict__ z) {
    extern __shared__ char smem[];
    __nv_bfloat16* As   = (__nv_bfloat16*)(smem + SA);
    float*         se_s = (float*)(smem + SSE);
    const uint32_t sbase = smem_u32(smem);

    const int tid = threadIdx.x, lane = tid & 31, wid = tid >> 5;
    const int qr = lane >> 2, qc = lane & 3;
    const int WM = wid & 1, WN = wid >> 1;          // 2 x 4 warp grid
    const int n0 = blockIdx.x * 128;

    // ---- A fill: z rows n0..n0+127 -> bf16 As[row][c]
    {
        const float* zb = z + ((size_t)(n0 >> 12)) * 1048576 + (n0 & 4095);
#pragma unroll 8
        for (int i = 0; i < 128; i++) {
            int u = tid + i * 256;
            int row = u & 127, c = u >> 7;
            As[row * RS + c] = __float2bfloat16(zb[(size_t)c * 4096 + row]);
        }
    }

    // ---- ldmatrix per-lane base addresses ----
    const int l7 = lane & 7;
    const int a_row  = 64 * WM + l7 + 8 * ((lane >> 3) & 1);
    const int a_koff = (lane >> 4) * 8;
    const uint32_t a_base = sbase + SA + (uint32_t)((a_row * RS + a_koff) * 2);
    const int bt = lane >> 3;
    const int b_rowoff = 8 * (bt >> 1) + l7;
    const int b_koff = 8 * (bt & 1);
    const uint32_t b_lane_off = (uint32_t)(((32 * WN + b_rowoff) * RS + b_koff) * 2);

    // ---- B tile async loader ----
    auto issueB = [&](int t) {
        const __nv_bfloat16* src = g_embh + (size_t)t * 128 * RS;
        uint32_t dbase = sbase + SB + (t & 1) * (BUFE * 2);
#pragma unroll
        for (int i = 0; i < 16; i++) {
            int u = tid + i * 256;
            int n = u >> 5, m = u & 31;
            cp16(dbase + (uint32_t)(n * RS * 2 + m * 16),
                 (const void*)(src + (size_t)n * RS + m * 8));
        }
        if (tid < 128) se_s[(t & 1) * 128 + tid] = g_se[t * 128 + tid];
    };

    issueB(0);
    CP_COMMIT();

    for (int t = 0; t < 16; t++) {
        if (t < 15) { issueB(t + 1); CP_COMMIT(); CP_WAIT1(); }
        else        { CP_WAIT0(); }
        __syncthreads();                            // tile t data visible

        const uint32_t bbuf = sbase + SB + (t & 1) * (BUFE * 2) + b_lane_off;
        float acc[4][4][4];
#pragma unroll
        for (int mf = 0; mf < 4; mf++)
#pragma unroll
            for (int nf = 0; nf < 4; nf++)
#pragma unroll
                for (int i = 0; i < 4; i++) acc[mf][nf][i] = 0.f;

#pragma unroll
        for (int ks = 0; ks < 16; ks++) {
            const uint32_t kb = (uint32_t)(ks * 32);
            uint32_t a[4][4], b[4][2];
#pragma unroll
            for (int mf = 0; mf < 4; mf++)
                ldm4(a[mf], a_base + (uint32_t)(16 * mf * RS * 2) + kb);
            {
                uint32_t bv[4];
                ldm4(bv, bbuf + kb);
                b[0][0] = bv[0]; b[0][1] = bv[1];
                b[1][0] = bv[2]; b[1][1] = bv[3];
                ldm4(bv, bbuf + (uint32_t)(16 * RS * 2) + kb);
                b[2][0] = bv[0]; b[2][1] = bv[1];
                b[3][0] = bv[2]; b[3][1] = bv[3];
            }
#pragma unroll
            for (int mf = 0; mf < 4; mf++)
#pragma unroll
                for (int nf = 0; nf < 4; nf++)
                    mma16816(acc[mf][nf], a[mf], b[nf]);
        }

        // ---- dump tt = se - 2*acc as fp16 (half2 = 4B per lane per row)
        const float* sep = se_s + (t & 1) * 128;
#pragma unroll
        for (int mf = 0; mf < 4; mf++) {
            const int r0 = n0 + 64 * WM + 16 * mf + qr;
#pragma unroll
            for (int nf = 0; nf < 4; nf++) {
                const int cb = 32 * WN + 8 * nf + 2 * qc;
                const float s0 = sep[cb], s1 = sep[cb + 1];
                const size_t col = (size_t)(t * 128 + cb);
                float2 v;
                v.x = fmaf(-2.f, acc[mf][nf][0], s0);
                v.y = fmaf(-2.f, acc[mf][nf][1], s1);
                *(__half2*)(g_tth + ((size_t)r0 << 11) + col) = __float22half2_rn(v);
                v.x = fmaf(-2.f, acc[mf][nf][2], s0);
                v.y = fmaf(-2.f, acc[mf][nf][3], s1);
                *(__half2*)(g_tth + ((size_t)(r0 + 8) << 11) + col) = __float22half2_rn(v);
            }
        }
        __syncthreads();    // all reads of buf done before issueB overwrites it
    }
}

// ===========================================================================
// Fused scan + exact rescore. One warp per row.
// Row kept as 32 packed half2 regs; tree-min via __hmin2 (fp16 min is
// monotone-equivalent to f32 min of the same values -> superset intact).
// Candidates: tt <= min + eps (f32 compares after unpack).
// Exact fp32 rescore per hit: bit-exact R1 sequence, lexicographic reduce.
// ===========================================================================
__global__ __launch_bounds__(256) void k_scan(const float* __restrict__ z,
                                              const float* __restrict__ emb) {
    __shared__ float zrow[8][256];
    const int tid = threadIdx.x, w = tid >> 5, lane = tid & 31;
    const int n0 = blockIdx.x * 8;
    const int bb = n0 >> 12;
    const float* zb = z + (size_t)bb * 1048576 + (n0 & 4095);
    {
        int r = tid & 7, cp = tid >> 3;
#pragma unroll
        for (int jj = 0; jj < 8; jj++) {
            int c = cp + jj * 32;
            zrow[r][c] = zb[(size_t)c * 4096 + r];
        }
    }
    __syncthreads();

    const int n = n0 + w;
    const float sz = g_sz[n];
    const float* zr = zrow[w];
    const __half* tp = g_tth + ((size_t)n << 11) + 4 * lane;

    // lane covers cols 128*j + 4*lane + {0..3}; packed as 2 half2 per j
    __half2 h2[32];
#pragma unroll
    for (int j = 0; j < 16; j++) {
        uint2 v = *(const uint2*)(tp + 128 * j);
        h2[2 * j]     = *(__half2*)&v.x;
        h2[2 * j + 1] = *(__half2*)&v.y;
    }

    // tree min over 32 half2 (depth 5), then intra-pair + warp reduce in f32
    __half2 m2[16];
#pragma unroll
    for (int i = 0; i < 16; i++) m2[i] = __hmin2(h2[i], h2[i + 16]);
#pragma unroll
    for (int s = 8; s > 0; s >>= 1)
#pragma unroll
        for (int i = 0; i < 8; i++)
            if (i < s) m2[i] = __hmin2(m2[i], m2[i + s]);
    float2 mf2 = __half22float2(m2[0]);
    float mn = fminf(mf2.x, mf2.y);
#pragma unroll
    for (int off = 16; off > 0; off >>= 1)
        mn = fminf(mn, __shfl_xor_sync(0xffffffffu, mn, off));

    const float thr = mn + FILT_EPS;
    unsigned long long mask = 0ull;
#pragma unroll
    for (int j = 0; j < 32; j++) {
        float2 f = __half22float2(h2[j]);
        if (f.x <= thr) mask |= (1ull << (2 * j));
        if (f.y <= thr) mask |= (1ull << (2 * j + 1));
    }

    float bd = 1e38f;
    int bi = 0x7fffffff;
    while (mask) {
        int b = __ffsll((long long)mask) - 1;   // b = 4*j + s
        mask &= mask - 1;
        int k = 128 * (b >> 2) + 4 * lane + (b & 3);
        const float* e = emb + (size_t)k * 256;
        float acc = 0.f;
#pragma unroll 8
        for (int c = 0; c < 256; c++) acc = fmaf(zr[c], e[c], acc);
        float d = (sz + g_se[k]) - 2.0f * acc;
        if (d < bd || (d == bd && k < bi)) { bd = d; bi = k; }
    }
#pragma unroll
    for (int off = 16; off > 0; off >>= 1) {
        float d2 = __shfl_down_sync(0xffffffffu, bd, off);
        int i2 = __shfl_down_sync(0xffffffffu, bi, off);
        if (d2 < bd || (d2 == bd && i2 < bi)) { bd = d2; bi = i2; }
    }
    if (lane == 0) g_idx[n] = bi;
}

// ===========================================================================
// gather + z_q_st + loss partials (2 rows per warp)
// ===========================================================================
__global__ __launch_bounds__(256) void k_gather(const float* __restrict__ z,
                                                const float* __restrict__ emb,
                                                float* __restrict__ out) {
    const int tid = threadIdx.x, lane = tid & 31, w = tid >> 5;
    const int n = blockIdx.x * 16 + w * 2;
    const int iA = g_idx[n], iB = g_idx[n + 1];
    const size_t eoA = (size_t)iA * 256 + lane * 8;
    const size_t eoB = (size_t)iB * 256 + lane * 8;
    const size_t zoA = (size_t)n * 256 + lane * 8;
    const size_t zoB = zoA + 256;

    float4 a0 = *(const float4*)(emb + eoA), a1 = *(const float4*)(emb + eoA + 4);
    float4 b0 = *(const float4*)(emb + eoB), b1 = *(const float4*)(emb + eoB + 4);
    float4 x0 = *(const float4*)(z + zoA),   x1 = *(const float4*)(z + zoA + 4);
    float4 y0 = *(const float4*)(z + zoB),   y1 = *(const float4*)(z + zoB + 4);

    float dA[8] = {a0.x - x0.x, a0.y - x0.y, a0.z - x0.z, a0.w - x0.w,
                   a1.x - x1.x, a1.y - x1.y, a1.z - x1.z, a1.w - x1.w};
    float dB[8] = {b0.x - y0.x, b0.y - y0.y, b0.z - y0.z, b0.w - y0.w,
                   b1.x - y1.x, b1.y - y1.y, b1.z - y1.z, b1.w - y1.w};

    float4 o;
    o.x = x0.x + dA[0]; o.y = x0.y + dA[1]; o.z = x0.z + dA[2]; o.w = x0.w + dA[3];
    *(float4*)(out + zoA) = o;
    o.x = x1.x + dA[4]; o.y = x1.y + dA[5]; o.z = x1.z + dA[6]; o.w = x1.w + dA[7];
    *(float4*)(out + zoA + 4) = o;
    o.x = y0.x + dB[0]; o.y = y0.y + dB[1]; o.z = y0.z + dB[2]; o.w = y0.w + dB[3];
    *(float4*)(out + zoB) = o;
    o.x = y1.x + dB[4]; o.y = y1.y + dB[5]; o.z = y1.z + dB[6]; o.w = y1.w + dB[7];
    *(float4*)(out + zoB + 4) = o;

    double s = 0.0;
#pragma unroll
    for (int i = 0; i < 8; i++) s += (double)dA[i] * dA[i] + (double)dB[i] * dB[i];
#pragma unroll
    for (int off = 16; off > 0; off >>= 1)
        s += __shfl_down_sync(0xffffffffu, s, off);

    __shared__ double sp[8];
    if (lane == 0) sp[w] = s;
    __syncthreads();
    if (tid == 0) {
        double t = 0.0;
#pragma unroll
        for (int i = 0; i < 8; i++) t += sp[i];
        g_part[blockIdx.x] = t;
    }
}

__global__ void k_final(float* __restrict__ out) {
    __shared__ double red[256];
    int tid = threadIdx.x;
    double s = 0.0;
    for (int i = tid; i < NPART; i += 256) s += g_part[i];
    red[tid] = s;
    __syncthreads();
    for (int st = 128; st > 0; st >>= 1) {
        if (tid < st) red[tid] += red[tid + st];
        __syncthreads();
    }
    if (tid == 0) {
        float m = (float)(red[0] / (double)ZQN);
        out[LOSS_OFF] = m + 0.25f * m;
    }
    for (int i = tid; i < NROWS; i += 256) out[IDX_OFF + i] = (float)g_idx[i];
}

// ===========================================================================
extern "C" void kernel_launch(void* const* d_in, const int* in_sizes, int n_in,
                              void* d_out, int out_size) {
    const float* z = (const float*)d_in[0];
    const float* emb = (const float*)d_in[1];
    float* out = (float*)d_out;

    k_se<<<16, 128>>>(emb);
    k_sz<<<128, 256>>>(z);
    k_cvt<<<128, 256>>>(emb);

    cudaFuncSetAttribute(k_filter, cudaFuncAttributeMaxDynamicSharedMemorySize, SMEM_F);
    k_filter<<<256, 256, SMEM_F>>>(z);

    k_scan<<<4096, 256>>>(z, emb);
    k_gather<<<2048, 256>>>(z, emb, out);
    k_final<<<1, 256>>>(out);
}